// round 1
// baseline (speedup 1.0000x reference)
#include <cuda_runtime.h>
#include <cuda_bf16.h>
#include <math.h>

// Problem constants (B=128, N=511, M=256, R=64, IN=512)
#define BATCH  128
#define NNODES 511
#define MDIM   256
#define RDIM   64
#define INDIM  512

// GEMM tiling
#define BM 64
#define BN 64
#define BK 16
#define SAS 66      // padded sA row stride (conflict-free stores)
#define NTH 256

// Persistent scratch (device globals; no allocation)
__device__ float g_h_buf[(size_t)NNODES * BATCH * MDIM];   // [node][b][m]
__device__ float g_c_buf[(size_t)NNODES * BATCH * MDIM];
__device__ float g_h1[(size_t)128 * BATCH * MDIM];         // cell1 h   [levelrow][m]
__device__ float g_c1[(size_t)128 * BATCH * MDIM];         // cell1 c
__device__ float g_ht[(size_t)128 * BATCH * MDIM];         // h_tilde

__device__ __forceinline__ float sigf(float x) { return 1.0f / (1.0f + expf(-x)); }

// Multi-accumulator tiled GEMM phase.
// acc[j][i][q] += sum_k A[row, k] * Bp[j][k*ldb + col]
// A rows come from per-row base pointers in shared (gather support).
template<int NACC>
__device__ __forceinline__ void gemm_phase(
    float (*acc)[4][4],
    const float* const* rowptr,
    const float* const (&Bp)[NACC],
    int ldb, int K,
    float* sA, float* sB, int tid)
{
    const int ty = tid >> 4, tx = tid & 15;
    const int ar = tid >> 2, akv = (tid & 3) * 4;
    const int bk = tid >> 4, bnv = (tid & 15) * 4;
    const float* aptr = rowptr[ar];
    for (int k0 = 0; k0 < K; k0 += BK) {
        float4 av = *reinterpret_cast<const float4*>(aptr + k0 + akv);
        sA[(akv + 0) * SAS + ar] = av.x;
        sA[(akv + 1) * SAS + ar] = av.y;
        sA[(akv + 2) * SAS + ar] = av.z;
        sA[(akv + 3) * SAS + ar] = av.w;
#pragma unroll
        for (int j = 0; j < NACC; j++) {
            float4 bv = *reinterpret_cast<const float4*>(Bp[j] + (size_t)(k0 + bk) * ldb + bnv);
            *reinterpret_cast<float4*>(&sB[(j * BK + bk) * BN + bnv]) = bv;
        }
        __syncthreads();
#pragma unroll
        for (int kk = 0; kk < BK; kk++) {
            float a0 = sA[kk * SAS + ty * 4 + 0];
            float a1 = sA[kk * SAS + ty * 4 + 1];
            float a2 = sA[kk * SAS + ty * 4 + 2];
            float a3 = sA[kk * SAS + ty * 4 + 3];
#pragma unroll
            for (int j = 0; j < NACC; j++) {
                float4 b = *reinterpret_cast<const float4*>(&sB[(j * BK + kk) * BN + tx * 4]);
                acc[j][0][0] += a0 * b.x; acc[j][0][1] += a0 * b.y; acc[j][0][2] += a0 * b.z; acc[j][0][3] += a0 * b.w;
                acc[j][1][0] += a1 * b.x; acc[j][1][1] += a1 * b.y; acc[j][1][2] += a1 * b.z; acc[j][1][3] += a1 * b.w;
                acc[j][2][0] += a2 * b.x; acc[j][2][1] += a2 * b.y; acc[j][2][2] += a2 * b.z; acc[j][2][3] += a2 * b.w;
                acc[j][3][0] += a3 * b.x; acc[j][3][1] += a3 * b.y; acc[j][3][2] += a3 * b.z; acc[j][3][3] += a3 * b.w;
            }
        }
        __syncthreads();
    }
}

// ---------------- Leaf kernel: nodes 255..510 ----------------
// h_tilde = 0; i = sig(x Wix + bix + bih); u = tanh(x Wux + ...); o = sig(x Wox + ...)
// c = i*u; h = o*tanh(c)
__global__ void __launch_bounds__(NTH)
k_leaf(const float* __restrict__ wte,
       const float* __restrict__ Wix, const float* __restrict__ Wux, const float* __restrict__ Wox,
       const float* __restrict__ bix, const float* __restrict__ bux, const float* __restrict__ boxb,
       const float* __restrict__ bih, const float* __restrict__ buh, const float* __restrict__ boh)
{
    __shared__ float sA[BK * SAS];
    __shared__ float sB[3 * BK * BN];
    __shared__ const float* rowptr[BM];
    const int tid = threadIdx.x;
    const int rb = blockIdx.x * BM;
    const int n0 = blockIdx.y * BN;

    float acc[3][4][4];
#pragma unroll
    for (int j = 0; j < 3; j++)
#pragma unroll
        for (int i = 0; i < 4; i++)
#pragma unroll
            for (int q = 0; q < 4; q++) acc[j][i][q] = 0.0f;

    if (tid < BM) {
        int r = rb + tid;
        int node = 255 + (r >> 7);
        int b = r & 127;
        rowptr[tid] = wte + (size_t)(b * NNODES + node) * INDIM;
    }
    __syncthreads();
    {
        const float* const Bp[3] = { Wix + n0, Wux + n0, Wox + n0 };
        gemm_phase<3>(acc, rowptr, Bp, MDIM, INDIM, sA, sB, tid);
    }
    const int ty = tid >> 4, tx = tid & 15;
    const int m0 = n0 + tx * 4;
#pragma unroll
    for (int i = 0; i < 4; i++) {
        int r = rb + ty * 4 + i;
        int node = 255 + (r >> 7);
        int b = r & 127;
        size_t base = (size_t)(node * BATCH + b) * MDIM + m0;
        float4 hv, cv;
        float* hp = (float*)&hv; float* cp = (float*)&cv;
#pragma unroll
        for (int q = 0; q < 4; q++) {
            int m = m0 + q;
            float iv = sigf(acc[0][i][q] + bix[m] + bih[m]);
            float uv = tanhf(acc[1][i][q] + bux[m] + buh[m]);
            float ov = sigf(acc[2][i][q] + boxb[m] + boh[m]);
            float c = iv * uv;
            cp[q] = c;
            hp[q] = ov * tanhf(c);
        }
        *reinterpret_cast<float4*>(&g_h_buf[base]) = hv;
        *reinterpret_cast<float4*>(&g_c_buf[base]) = cv;
    }
}

// ---------------- Cell 1: x = [h(2n+1), rel(2n+1)], h=c=0 (f-gate dead) ----------------
__global__ void __launch_bounds__(NTH)
k_cell1(const float* __restrict__ rel,
        const float* __restrict__ Wsih,
        const float* __restrict__ bsi, const float* __restrict__ bsh,
        int nodeBase)
{
    __shared__ float sA[BK * SAS];
    __shared__ float sB[3 * BK * BN];
    __shared__ const float* rowptr[BM];
    const int tid = threadIdx.x;
    const int rb = blockIdx.x * BM;
    const int n0 = blockIdx.y * BN;

    float acc[3][4][4];  // i, g, o
#pragma unroll
    for (int j = 0; j < 3; j++)
#pragma unroll
        for (int i = 0; i < 4; i++)
#pragma unroll
            for (int q = 0; q < 4; q++) acc[j][i][q] = 0.0f;

    if (tid < BM) {
        int r = rb + tid;
        int node = nodeBase + (r >> 7);
        int b = r & 127;
        int c0 = 2 * node + 1;
        rowptr[tid] = g_h_buf + (size_t)(c0 * BATCH + b) * MDIM;
    }
    __syncthreads();
    {
        const float* const Bp[3] = { Wsih + n0, Wsih + 512 + n0, Wsih + 768 + n0 };
        gemm_phase<3>(acc, rowptr, Bp, 1024, MDIM, sA, sB, tid);
    }
    if (tid < BM) {
        int r = rb + tid;
        int node = nodeBase + (r >> 7);
        int b = r & 127;
        int c0 = 2 * node + 1;
        rowptr[tid] = rel + (size_t)(b * NNODES + c0) * RDIM;
    }
    __syncthreads();
    {
        const float* const Bp[3] = { Wsih + 256 * 1024 + n0, Wsih + 256 * 1024 + 512 + n0,
                                     Wsih + 256 * 1024 + 768 + n0 };
        gemm_phase<3>(acc, rowptr, Bp, 1024, RDIM, sA, sB, tid);
    }
    const int ty = tid >> 4, tx = tid & 15;
    const int m0 = n0 + tx * 4;
#pragma unroll
    for (int i = 0; i < 4; i++) {
        int r = rb + ty * 4 + i;
        size_t base = (size_t)r * MDIM + m0;
        float4 hv, cv;
        float* hp = (float*)&hv; float* cp = (float*)&cv;
#pragma unroll
        for (int q = 0; q < 4; q++) {
            int m = m0 + q;
            float iv = sigf(acc[0][i][q] + bsi[m] + bsh[m]);
            float gv = tanhf(acc[1][i][q] + bsi[512 + m] + bsh[512 + m]);
            float ov = sigf(acc[2][i][q] + bsi[768 + m] + bsh[768 + m]);
            float c1 = iv * gv;
            cp[q] = c1;
            hp[q] = ov * tanhf(c1);
        }
        *reinterpret_cast<float4*>(&g_h1[base]) = hv;
        *reinterpret_cast<float4*>(&g_c1[base]) = cv;
    }
}

// ---------------- Cell 2: x = [h(2n+2), rel(2n+2)], h=h1, c=c1 ----------------
__global__ void __launch_bounds__(NTH)
k_cell2(const float* __restrict__ rel,
        const float* __restrict__ Wsih, const float* __restrict__ Wshh,
        const float* __restrict__ bsi, const float* __restrict__ bsh,
        int nodeBase)
{
    __shared__ float sA[BK * SAS];
    __shared__ float sB[4 * BK * BN];
    __shared__ const float* rowptr[BM];
    const int tid = threadIdx.x;
    const int rb = blockIdx.x * BM;
    const int n0 = blockIdx.y * BN;

    float acc[4][4][4];  // i, f, g, o
#pragma unroll
    for (int j = 0; j < 4; j++)
#pragma unroll
        for (int i = 0; i < 4; i++)
#pragma unroll
            for (int q = 0; q < 4; q++) acc[j][i][q] = 0.0f;

    if (tid < BM) {
        int r = rb + tid;
        int node = nodeBase + (r >> 7);
        int b = r & 127;
        int c1n = 2 * node + 2;
        rowptr[tid] = g_h_buf + (size_t)(c1n * BATCH + b) * MDIM;
    }
    __syncthreads();
    {
        const float* const Bp[4] = { Wsih + n0, Wsih + 256 + n0, Wsih + 512 + n0, Wsih + 768 + n0 };
        gemm_phase<4>(acc, rowptr, Bp, 1024, MDIM, sA, sB, tid);
    }
    if (tid < BM) {
        int r = rb + tid;
        int node = nodeBase + (r >> 7);
        int b = r & 127;
        int c1n = 2 * node + 2;
        rowptr[tid] = rel + (size_t)(b * NNODES + c1n) * RDIM;
    }
    __syncthreads();
    {
        const float* const Bp[4] = { Wsih + 256 * 1024 + n0, Wsih + 256 * 1024 + 256 + n0,
                                     Wsih + 256 * 1024 + 512 + n0, Wsih + 256 * 1024 + 768 + n0 };
        gemm_phase<4>(acc, rowptr, Bp, 1024, RDIM, sA, sB, tid);
    }
    if (tid < BM) {
        int r = rb + tid;
        rowptr[tid] = g_h1 + (size_t)r * MDIM;
    }
    __syncthreads();
    {
        const float* const Bp[4] = { Wshh + n0, Wshh + 256 + n0, Wshh + 512 + n0, Wshh + 768 + n0 };
        gemm_phase<4>(acc, rowptr, Bp, 1024, MDIM, sA, sB, tid);
    }
    const int ty = tid >> 4, tx = tid & 15;
    const int m0 = n0 + tx * 4;
#pragma unroll
    for (int i = 0; i < 4; i++) {
        int r = rb + ty * 4 + i;
        size_t base = (size_t)r * MDIM + m0;
        float4 c1v = *reinterpret_cast<const float4*>(&g_c1[base]);
        const float* c1p = (const float*)&c1v;
        float4 hv;
        float* hp = (float*)&hv;
#pragma unroll
        for (int q = 0; q < 4; q++) {
            int m = m0 + q;
            float iv = sigf(acc[0][i][q] + bsi[m] + bsh[m]);
            float fv = sigf(acc[1][i][q] + bsi[256 + m] + bsh[256 + m]);
            float gv = tanhf(acc[2][i][q] + bsi[512 + m] + bsh[512 + m]);
            float ov = sigf(acc[3][i][q] + bsi[768 + m] + bsh[768 + m]);
            float c2 = fv * c1p[q] + iv * gv;
            hp[q] = ov * tanhf(c2);
        }
        *reinterpret_cast<float4*>(&g_ht[base]) = hv;
    }
}

// ---------------- Tree gates: i,u,o,f0,f1 -> c, h ----------------
__global__ void __launch_bounds__(NTH)
k_gates(const float* __restrict__ wte,
        const float* __restrict__ Wix, const float* __restrict__ Wux,
        const float* __restrict__ Wox, const float* __restrict__ Wfx,
        const float* __restrict__ Wih, const float* __restrict__ Wuh,
        const float* __restrict__ Woh, const float* __restrict__ Wfh,
        const float* __restrict__ bix, const float* __restrict__ bux,
        const float* __restrict__ boxb, const float* __restrict__ bfx,
        const float* __restrict__ bih, const float* __restrict__ buh,
        const float* __restrict__ boh, const float* __restrict__ bfh,
        int nodeBase, float* __restrict__ outp)
{
    __shared__ float sA[BK * SAS];
    __shared__ float sB[4 * BK * BN];
    __shared__ const float* rowptr[BM];
    const int tid = threadIdx.x;
    const int rb = blockIdx.x * BM;
    const int n0 = blockIdx.y * BN;

    float acc[4][4][4];   // i, u, o, fx
    float accF0[1][4][4], accF1[1][4][4];
#pragma unroll
    for (int j = 0; j < 4; j++)
#pragma unroll
        for (int i = 0; i < 4; i++)
#pragma unroll
            for (int q = 0; q < 4; q++) acc[j][i][q] = 0.0f;
#pragma unroll
    for (int i = 0; i < 4; i++)
#pragma unroll
        for (int q = 0; q < 4; q++) { accF0[0][i][q] = 0.0f; accF1[0][i][q] = 0.0f; }

    // phase 1: x part (K = 512)
    if (tid < BM) {
        int r = rb + tid;
        int node = nodeBase + (r >> 7);
        int b = r & 127;
        rowptr[tid] = wte + (size_t)(b * NNODES + node) * INDIM;
    }
    __syncthreads();
    {
        const float* const Bp[4] = { Wix + n0, Wux + n0, Wox + n0, Wfx + n0 };
        gemm_phase<4>(acc, rowptr, Bp, MDIM, INDIM, sA, sB, tid);
    }
    // phase 2: h_tilde part for i,u,o (K = 256)
    if (tid < BM) {
        int r = rb + tid;
        rowptr[tid] = g_ht + (size_t)r * MDIM;
    }
    __syncthreads();
    {
        const float* const Bp[3] = { Wih + n0, Wuh + n0, Woh + n0 };
        gemm_phase<3>(acc, rowptr, Bp, MDIM, MDIM, sA, sB, tid);
    }
    // phase 3: f0 = h(2n+1) @ Wfh
    if (tid < BM) {
        int r = rb + tid;
        int node = nodeBase + (r >> 7);
        int b = r & 127;
        rowptr[tid] = g_h_buf + (size_t)((2 * node + 1) * BATCH + b) * MDIM;
    }
    __syncthreads();
    {
        const float* const Bp[1] = { Wfh + n0 };
        gemm_phase<1>(accF0, rowptr, Bp, MDIM, MDIM, sA, sB, tid);
    }
    // phase 4: f1 = h(2n+2) @ Wfh
    if (tid < BM) {
        int r = rb + tid;
        int node = nodeBase + (r >> 7);
        int b = r & 127;
        rowptr[tid] = g_h_buf + (size_t)((2 * node + 2) * BATCH + b) * MDIM;
    }
    __syncthreads();
    {
        const float* const Bp[1] = { Wfh + n0 };
        gemm_phase<1>(accF1, rowptr, Bp, MDIM, MDIM, sA, sB, tid);
    }

    const int ty = tid >> 4, tx = tid & 15;
    const int m0 = n0 + tx * 4;
#pragma unroll
    for (int i = 0; i < 4; i++) {
        int r = rb + ty * 4 + i;
        int node = nodeBase + (r >> 7);
        int b = r & 127;
        int c0n = 2 * node + 1;
        int c1n = 2 * node + 2;
        size_t base  = (size_t)(node * BATCH + b) * MDIM + m0;
        size_t base0 = (size_t)(c0n * BATCH + b) * MDIM + m0;
        size_t base1 = (size_t)(c1n * BATCH + b) * MDIM + m0;
        float4 cc0 = *reinterpret_cast<const float4*>(&g_c_buf[base0]);
        float4 cc1 = *reinterpret_cast<const float4*>(&g_c_buf[base1]);
        const float* cc0p = (const float*)&cc0;
        const float* cc1p = (const float*)&cc1;
        float4 hv, cv;
        float* hp = (float*)&hv; float* cp = (float*)&cv;
#pragma unroll
        for (int q = 0; q < 4; q++) {
            int m = m0 + q;
            float iv = sigf(acc[0][i][q] + bix[m] + bih[m]);
            float uv = tanhf(acc[1][i][q] + bux[m] + buh[m]);
            float ov = sigf(acc[2][i][q] + boxb[m] + boh[m]);
            float fx = acc[3][i][q] + bfx[m] + bfh[m];
            float f0 = sigf(fx + accF0[0][i][q]);
            float f1 = sigf(fx + accF1[0][i][q]);
            float c = iv * uv + f0 * cc0p[q] + f1 * cc1p[q];
            cp[q] = c;
            hp[q] = ov * tanhf(c);
        }
        *reinterpret_cast<float4*>(&g_h_buf[base]) = hv;
        *reinterpret_cast<float4*>(&g_c_buf[base]) = cv;
        if (outp) {
            *reinterpret_cast<float4*>(&outp[(size_t)r * MDIM + m0]) = hv;
        }
    }
}

extern "C" void kernel_launch(void* const* d_in, const int* in_sizes, int n_in,
                              void* d_out, int out_size)
{
    // Size-based input matching (robust to metadata vs signature ordering;
    // relative order within each size class is identical in both).
    const float* wte = nullptr;
    const float* rel = nullptr;
    const float* Wx[4];  int nWx = 0;   // ix, fx, ux, ox
    const float* Wh[4];  int nWh = 0;   // ih, fh, uh, oh
    const float* b256[8]; int nb = 0;   // bix,bfx,bux,box,bih,bfh,buh,boh
    const float* Wsih = nullptr;
    const float* Wshh = nullptr;
    const float* bseq[2]; int nbs = 0;  // b_seq_ih, b_seq_hh

    for (int i = 0; i < n_in; i++) {
        int s = in_sizes[i];
        const float* p = (const float*)d_in[i];
        switch (s) {
            case 33488896: wte = p; break;                 // 128*511*512
            case 4186112:  rel = p; break;                 // 128*511*64
            case 131072:   if (nWx < 4) Wx[nWx++] = p; break;   // 512*256
            case 65536:    if (nWh < 4) Wh[nWh++] = p; break;   // 256*256
            case 256:      if (nb < 8) b256[nb++] = p; break;
            case 327680:   Wsih = p; break;                // 320*1024
            case 262144:   Wshh = p; break;                // 256*1024
            case 1024:     if (nbs < 2) bseq[nbs++] = p; break;
            default: break;  // n_nodes (size 1) ignored: compile-time constant
        }
    }
    const float *Wix = Wx[0], *Wfx = Wx[1], *Wux = Wx[2], *Wox = Wx[3];
    const float *Wih = Wh[0], *Wfh = Wh[1], *Wuh = Wh[2], *Woh = Wh[3];
    const float *bix = b256[0], *bfx = b256[1], *bux = b256[2], *boxb = b256[3];
    const float *bih = b256[4], *bfh = b256[5], *buh = b256[6], *boh = b256[7];
    float* out = (float*)d_out;

    dim3 blk(NTH);

    // Level 8: all 256 leaves at once (32768 rows)
    k_leaf<<<dim3(512, 4), blk>>>(wte, Wix, Wux, Wox, bix, bux, boxb, bih, buh, boh);

    // Levels 7..0 (internal nodes)
    for (int L = 7; L >= 0; --L) {
        int P = 1 << L;
        int nodeBase = P - 1;
        int rowBlocks = (P * BATCH) / BM;
        dim3 grd(rowBlocks, 4);
        k_cell1<<<grd, blk>>>(rel, Wsih, bseq[0], bseq[1], nodeBase);
        k_cell2<<<grd, blk>>>(rel, Wsih, Wshh, bseq[0], bseq[1], nodeBase);
        k_gates<<<grd, blk>>>(wte, Wix, Wux, Wox, Wfx, Wih, Wuh, Woh, Wfh,
                              bix, bux, boxb, bfx, bih, buh, boh, bfh,
                              nodeBase, (L == 0) ? out : nullptr);
    }
}

// round 2
// speedup vs baseline: 1.2072x; 1.2072x over previous
#include <cuda_runtime.h>
#include <cuda_bf16.h>
#include <math.h>

// Problem constants (B=128, N=511, M=256, R=64, IN=512)
#define BATCH  128
#define NNODES 511
#define MDIM   256
#define RDIM   64
#define INDIM  512

// GEMM tiling
#define BM 64
#define BN 64
#define BK 16
#define SAS 66      // padded sA row stride (conflict-free stores)
#define NTH 256

typedef unsigned long long ull;

// Persistent scratch (device globals; no allocation)
__device__ float g_h_buf[(size_t)NNODES * BATCH * MDIM];   // [node][b][m]
__device__ float g_c_buf[(size_t)NNODES * BATCH * MDIM];
__device__ float g_h1[(size_t)128 * BATCH * MDIM];         // cell1 h   [levelrow][m]
__device__ float g_c1[(size_t)128 * BATCH * MDIM];         // cell1 c
__device__ float g_ht[(size_t)128 * BATCH * MDIM];         // h_tilde

__device__ __forceinline__ float sigf(float x) { return 1.0f / (1.0f + expf(-x)); }

// ---- packed f32x2 helpers (sm_103a FFMA2; ptxas never auto-emits this) ----
__device__ __forceinline__ ull pack2(float x) {
    ull r;
    unsigned u = __float_as_uint(x);
    asm("mov.b64 %0, {%1, %1};" : "=l"(r) : "r"(u));
    return r;
}
__device__ __forceinline__ void ffma2(ull& d, ull a, ull b) {
    asm("fma.rn.f32x2 %0, %1, %2, %0;" : "+l"(d) : "l"(a), "l"(b));
}
__device__ __forceinline__ void unp2(ull v, float& lo, float& hi) {
    unsigned l, h;
    asm("mov.b64 {%0, %1}, %2;" : "=r"(l), "=r"(h) : "l"(v));
    lo = __uint_as_float(l);
    hi = __uint_as_float(h);
}

// Multi-accumulator tiled GEMM phase with double-buffered smem (1 sync per
// BK-step) and register prefetch. acc[j][i][p] holds packed column pairs:
// lanes (2p, 2p+1). A rows come from per-row base pointers (gather support).
template<int NACC>
__device__ __forceinline__ void gemm_phase(
    ull (*acc)[4][2],
    const float* const* rowptr,
    const float* const (&Bp)[NACC],
    int ldb, int K,
    float* sA, float* sB, int tid)
{
    const int ty = tid >> 4, tx = tid & 15;
    const int ar = tid >> 2, akv = (tid & 3) * 4;
    const int bk = tid >> 4, bnv = (tid & 15) * 4;
    const float* aptr = rowptr[ar];
    const int ASZ = BK * SAS;
    const int BSZ = NACC * BK * BN;

    // prefetch tile 0
    float4 av = *reinterpret_cast<const float4*>(aptr + akv);
    float4 bv[NACC];
#pragma unroll
    for (int j = 0; j < NACC; j++)
        bv[j] = *reinterpret_cast<const float4*>(Bp[j] + (size_t)bk * ldb + bnv);

    // store tile 0 into buffer 0
    sA[(akv + 0) * SAS + ar] = av.x;
    sA[(akv + 1) * SAS + ar] = av.y;
    sA[(akv + 2) * SAS + ar] = av.z;
    sA[(akv + 3) * SAS + ar] = av.w;
#pragma unroll
    for (int j = 0; j < NACC; j++)
        *reinterpret_cast<float4*>(&sB[(j * BK + bk) * BN + bnv]) = bv[j];
    __syncthreads();

    int cur = 0;
    for (int k0 = 0; k0 < K; k0 += BK) {
        const bool more = (k0 + BK) < K;
        if (more) {
            av = *reinterpret_cast<const float4*>(aptr + k0 + BK + akv);
#pragma unroll
            for (int j = 0; j < NACC; j++)
                bv[j] = *reinterpret_cast<const float4*>(Bp[j] + (size_t)(k0 + BK + bk) * ldb + bnv);
        }
        const float* cA = sA + cur * ASZ;
        const float* cB = sB + cur * BSZ;
#pragma unroll
        for (int kk = 0; kk < BK; kk++) {
            ull a0 = pack2(cA[kk * SAS + ty * 4 + 0]);
            ull a1 = pack2(cA[kk * SAS + ty * 4 + 1]);
            ull a2 = pack2(cA[kk * SAS + ty * 4 + 2]);
            ull a3 = pack2(cA[kk * SAS + ty * 4 + 3]);
#pragma unroll
            for (int j = 0; j < NACC; j++) {
                ulonglong2 b = *reinterpret_cast<const ulonglong2*>(cB + (j * BK + kk) * BN + tx * 4);
                ffma2(acc[j][0][0], a0, b.x); ffma2(acc[j][0][1], a0, b.y);
                ffma2(acc[j][1][0], a1, b.x); ffma2(acc[j][1][1], a1, b.y);
                ffma2(acc[j][2][0], a2, b.x); ffma2(acc[j][2][1], a2, b.y);
                ffma2(acc[j][3][0], a3, b.x); ffma2(acc[j][3][1], a3, b.y);
            }
        }
        if (more) {
            const int nxt = cur ^ 1;
            float* nA = sA + nxt * ASZ;
            float* nB = sB + nxt * BSZ;
            nA[(akv + 0) * SAS + ar] = av.x;
            nA[(akv + 1) * SAS + ar] = av.y;
            nA[(akv + 2) * SAS + ar] = av.z;
            nA[(akv + 3) * SAS + ar] = av.w;
#pragma unroll
            for (int j = 0; j < NACC; j++)
                *reinterpret_cast<float4*>(&nB[(j * BK + bk) * BN + bnv]) = bv[j];
            __syncthreads();
            cur = nxt;
        }
    }
}

// ---------------- Leaf kernel: nodes 255..510 ----------------
__global__ void __launch_bounds__(NTH)
k_leaf(const float* __restrict__ wte,
       const float* __restrict__ Wix, const float* __restrict__ Wux, const float* __restrict__ Wox,
       const float* __restrict__ bix, const float* __restrict__ bux, const float* __restrict__ boxb,
       const float* __restrict__ bih, const float* __restrict__ buh, const float* __restrict__ boh)
{
    __shared__ __align__(16) float sA[2 * BK * SAS];
    __shared__ __align__(16) float sB[2 * 3 * BK * BN];
    __shared__ const float* rowptr[BM];
    const int tid = threadIdx.x;
    const int rb = blockIdx.x * BM;
    const int n0 = blockIdx.y * BN;

    ull acc[3][4][2];
#pragma unroll
    for (int j = 0; j < 3; j++)
#pragma unroll
        for (int i = 0; i < 4; i++) { acc[j][i][0] = 0ull; acc[j][i][1] = 0ull; }

    if (tid < BM) {
        int r = rb + tid;
        int node = 255 + (r >> 7);
        int b = r & 127;
        rowptr[tid] = wte + (size_t)(b * NNODES + node) * INDIM;
    }
    __syncthreads();
    {
        const float* const Bp[3] = { Wix + n0, Wux + n0, Wox + n0 };
        gemm_phase<3>(acc, rowptr, Bp, MDIM, INDIM, sA, sB, tid);
    }
    const int ty = tid >> 4, tx = tid & 15;
    const int m0 = n0 + tx * 4;
#pragma unroll
    for (int i = 0; i < 4; i++) {
        int r = rb + ty * 4 + i;
        int node = 255 + (r >> 7);
        int b = r & 127;
        size_t base = (size_t)(node * BATCH + b) * MDIM + m0;
        float A[3][4];
#pragma unroll
        for (int j = 0; j < 3; j++) {
            unp2(acc[j][i][0], A[j][0], A[j][1]);
            unp2(acc[j][i][1], A[j][2], A[j][3]);
        }
        float4 hv, cv;
        float* hp = (float*)&hv; float* cp = (float*)&cv;
#pragma unroll
        for (int q = 0; q < 4; q++) {
            int m = m0 + q;
            float iv = sigf(A[0][q] + bix[m] + bih[m]);
            float uv = tanhf(A[1][q] + bux[m] + buh[m]);
            float ov = sigf(A[2][q] + boxb[m] + boh[m]);
            float c = iv * uv;
            cp[q] = c;
            hp[q] = ov * tanhf(c);
        }
        *reinterpret_cast<float4*>(&g_h_buf[base]) = hv;
        *reinterpret_cast<float4*>(&g_c_buf[base]) = cv;
    }
}

// ---------------- Cell 1: x = [h(2n+1), rel(2n+1)], h=c=0 (f-gate dead) ----------------
__global__ void __launch_bounds__(NTH)
k_cell1(const float* __restrict__ rel,
        const float* __restrict__ Wsih,
        const float* __restrict__ bsi, const float* __restrict__ bsh,
        int nodeBase)
{
    __shared__ __align__(16) float sA[2 * BK * SAS];
    __shared__ __align__(16) float sB[2 * 3 * BK * BN];
    __shared__ const float* rowptr[BM];
    const int tid = threadIdx.x;
    const int rb = blockIdx.x * BM;
    const int n0 = blockIdx.y * BN;

    ull acc[3][4][2];  // i, g, o
#pragma unroll
    for (int j = 0; j < 3; j++)
#pragma unroll
        for (int i = 0; i < 4; i++) { acc[j][i][0] = 0ull; acc[j][i][1] = 0ull; }

    if (tid < BM) {
        int r = rb + tid;
        int node = nodeBase + (r >> 7);
        int b = r & 127;
        int c0 = 2 * node + 1;
        rowptr[tid] = g_h_buf + (size_t)(c0 * BATCH + b) * MDIM;
    }
    __syncthreads();
    {
        const float* const Bp[3] = { Wsih + n0, Wsih + 512 + n0, Wsih + 768 + n0 };
        gemm_phase<3>(acc, rowptr, Bp, 1024, MDIM, sA, sB, tid);
    }
    if (tid < BM) {
        int r = rb + tid;
        int node = nodeBase + (r >> 7);
        int b = r & 127;
        int c0 = 2 * node + 1;
        rowptr[tid] = rel + (size_t)(b * NNODES + c0) * RDIM;
    }
    __syncthreads();
    {
        const float* const Bp[3] = { Wsih + 256 * 1024 + n0, Wsih + 256 * 1024 + 512 + n0,
                                     Wsih + 256 * 1024 + 768 + n0 };
        gemm_phase<3>(acc, rowptr, Bp, 1024, RDIM, sA, sB, tid);
    }
    const int ty = tid >> 4, tx = tid & 15;
    const int m0 = n0 + tx * 4;
#pragma unroll
    for (int i = 0; i < 4; i++) {
        int r = rb + ty * 4 + i;
        size_t base = (size_t)r * MDIM + m0;
        float A[3][4];
#pragma unroll
        for (int j = 0; j < 3; j++) {
            unp2(acc[j][i][0], A[j][0], A[j][1]);
            unp2(acc[j][i][1], A[j][2], A[j][3]);
        }
        float4 hv, cv;
        float* hp = (float*)&hv; float* cp = (float*)&cv;
#pragma unroll
        for (int q = 0; q < 4; q++) {
            int m = m0 + q;
            float iv = sigf(A[0][q] + bsi[m] + bsh[m]);
            float gv = tanhf(A[1][q] + bsi[512 + m] + bsh[512 + m]);
            float ov = sigf(A[2][q] + bsi[768 + m] + bsh[768 + m]);
            float c1 = iv * gv;
            cp[q] = c1;
            hp[q] = ov * tanhf(c1);
        }
        *reinterpret_cast<float4*>(&g_h1[base]) = hv;
        *reinterpret_cast<float4*>(&g_c1[base]) = cv;
    }
}

// ---------------- Cell 2: x = [h(2n+2), rel(2n+2)], h=h1, c=c1 ----------------
__global__ void __launch_bounds__(NTH)
k_cell2(const float* __restrict__ rel,
        const float* __restrict__ Wsih, const float* __restrict__ Wshh,
        const float* __restrict__ bsi, const float* __restrict__ bsh,
        int nodeBase)
{
    __shared__ __align__(16) float sA[2 * BK * SAS];
    __shared__ __align__(16) float sB[2 * 4 * BK * BN];
    __shared__ const float* rowptr[BM];
    const int tid = threadIdx.x;
    const int rb = blockIdx.x * BM;
    const int n0 = blockIdx.y * BN;

    ull acc[4][4][2];  // i, f, g, o
#pragma unroll
    for (int j = 0; j < 4; j++)
#pragma unroll
        for (int i = 0; i < 4; i++) { acc[j][i][0] = 0ull; acc[j][i][1] = 0ull; }

    if (tid < BM) {
        int r = rb + tid;
        int node = nodeBase + (r >> 7);
        int b = r & 127;
        int c1n = 2 * node + 2;
        rowptr[tid] = g_h_buf + (size_t)(c1n * BATCH + b) * MDIM;
    }
    __syncthreads();
    {
        const float* const Bp[4] = { Wsih + n0, Wsih + 256 + n0, Wsih + 512 + n0, Wsih + 768 + n0 };
        gemm_phase<4>(acc, rowptr, Bp, 1024, MDIM, sA, sB, tid);
    }
    if (tid < BM) {
        int r = rb + tid;
        int node = nodeBase + (r >> 7);
        int b = r & 127;
        int c1n = 2 * node + 2;
        rowptr[tid] = rel + (size_t)(b * NNODES + c1n) * RDIM;
    }
    __syncthreads();
    {
        const float* const Bp[4] = { Wsih + 256 * 1024 + n0, Wsih + 256 * 1024 + 256 + n0,
                                     Wsih + 256 * 1024 + 512 + n0, Wsih + 256 * 1024 + 768 + n0 };
        gemm_phase<4>(acc, rowptr, Bp, 1024, RDIM, sA, sB, tid);
    }
    if (tid < BM) {
        int r = rb + tid;
        rowptr[tid] = g_h1 + (size_t)r * MDIM;
    }
    __syncthreads();
    {
        const float* const Bp[4] = { Wshh + n0, Wshh + 256 + n0, Wshh + 512 + n0, Wshh + 768 + n0 };
        gemm_phase<4>(acc, rowptr, Bp, 1024, MDIM, sA, sB, tid);
    }
    const int ty = tid >> 4, tx = tid & 15;
    const int m0 = n0 + tx * 4;
#pragma unroll
    for (int i = 0; i < 4; i++) {
        int r = rb + ty * 4 + i;
        size_t base = (size_t)r * MDIM + m0;
        float A[4][4];
#pragma unroll
        for (int j = 0; j < 4; j++) {
            unp2(acc[j][i][0], A[j][0], A[j][1]);
            unp2(acc[j][i][1], A[j][2], A[j][3]);
        }
        float4 c1v = *reinterpret_cast<const float4*>(&g_c1[base]);
        const float* c1p = (const float*)&c1v;
        float4 hv;
        float* hp = (float*)&hv;
#pragma unroll
        for (int q = 0; q < 4; q++) {
            int m = m0 + q;
            float iv = sigf(A[0][q] + bsi[m] + bsh[m]);
            float fv = sigf(A[1][q] + bsi[256 + m] + bsh[256 + m]);
            float gv = tanhf(A[2][q] + bsi[512 + m] + bsh[512 + m]);
            float ov = sigf(A[3][q] + bsi[768 + m] + bsh[768 + m]);
            float c2 = fv * c1p[q] + iv * gv;
            hp[q] = ov * tanhf(c2);
        }
        *reinterpret_cast<float4*>(&g_ht[base]) = hv;
    }
}

// ---------------- Tree gates: i,u,o,f0,f1 -> c, h ----------------
__global__ void __launch_bounds__(NTH)
k_gates(const float* __restrict__ wte,
        const float* __restrict__ Wix, const float* __restrict__ Wux,
        const float* __restrict__ Wox, const float* __restrict__ Wfx,
        const float* __restrict__ Wih, const float* __restrict__ Wuh,
        const float* __restrict__ Woh, const float* __restrict__ Wfh,
        const float* __restrict__ bix, const float* __restrict__ bux,
        const float* __restrict__ boxb, const float* __restrict__ bfx,
        const float* __restrict__ bih, const float* __restrict__ buh,
        const float* __restrict__ boh, const float* __restrict__ bfh,
        int nodeBase, float* __restrict__ outp)
{
    __shared__ __align__(16) float sA[2 * BK * SAS];
    __shared__ __align__(16) float sB[2 * 4 * BK * BN];
    __shared__ const float* rowptr[BM];
    const int tid = threadIdx.x;
    const int rb = blockIdx.x * BM;
    const int n0 = blockIdx.y * BN;

    ull acc[4][4][2];   // i, u, o, fx
    ull accF0[1][4][2], accF1[1][4][2];
#pragma unroll
    for (int j = 0; j < 4; j++)
#pragma unroll
        for (int i = 0; i < 4; i++) { acc[j][i][0] = 0ull; acc[j][i][1] = 0ull; }
#pragma unroll
    for (int i = 0; i < 4; i++) {
        accF0[0][i][0] = 0ull; accF0[0][i][1] = 0ull;
        accF1[0][i][0] = 0ull; accF1[0][i][1] = 0ull;
    }

    // phase 1: x part (K = 512)
    if (tid < BM) {
        int r = rb + tid;
        int node = nodeBase + (r >> 7);
        int b = r & 127;
        rowptr[tid] = wte + (size_t)(b * NNODES + node) * INDIM;
    }
    __syncthreads();
    {
        const float* const Bp[4] = { Wix + n0, Wux + n0, Wox + n0, Wfx + n0 };
        gemm_phase<4>(acc, rowptr, Bp, MDIM, INDIM, sA, sB, tid);
    }
    // phase 2: h_tilde part for i,u,o (K = 256)
    if (tid < BM) {
        int r = rb + tid;
        rowptr[tid] = g_ht + (size_t)r * MDIM;
    }
    __syncthreads();
    {
        const float* const Bp[3] = { Wih + n0, Wuh + n0, Woh + n0 };
        gemm_phase<3>(acc, rowptr, Bp, MDIM, MDIM, sA, sB, tid);
    }
    // phase 3: f0 = h(2n+1) @ Wfh
    if (tid < BM) {
        int r = rb + tid;
        int node = nodeBase + (r >> 7);
        int b = r & 127;
        rowptr[tid] = g_h_buf + (size_t)((2 * node + 1) * BATCH + b) * MDIM;
    }
    __syncthreads();
    {
        const float* const Bp[1] = { Wfh + n0 };
        gemm_phase<1>(accF0, rowptr, Bp, MDIM, MDIM, sA, sB, tid);
    }
    // phase 4: f1 = h(2n+2) @ Wfh
    if (tid < BM) {
        int r = rb + tid;
        int node = nodeBase + (r >> 7);
        int b = r & 127;
        rowptr[tid] = g_h_buf + (size_t)((2 * node + 2) * BATCH + b) * MDIM;
    }
    __syncthreads();
    {
        const float* const Bp[1] = { Wfh + n0 };
        gemm_phase<1>(accF1, rowptr, Bp, MDIM, MDIM, sA, sB, tid);
    }

    const int ty = tid >> 4, tx = tid & 15;
    const int m0 = n0 + tx * 4;
#pragma unroll
    for (int i = 0; i < 4; i++) {
        int r = rb + ty * 4 + i;
        int node = nodeBase + (r >> 7);
        int b = r & 127;
        int c0n = 2 * node + 1;
        int c1n = 2 * node + 2;
        size_t base  = (size_t)(node * BATCH + b) * MDIM + m0;
        size_t base0 = (size_t)(c0n * BATCH + b) * MDIM + m0;
        size_t base1 = (size_t)(c1n * BATCH + b) * MDIM + m0;
        float A[4][4], F0[4], F1[4];
#pragma unroll
        for (int j = 0; j < 4; j++) {
            unp2(acc[j][i][0], A[j][0], A[j][1]);
            unp2(acc[j][i][1], A[j][2], A[j][3]);
        }
        unp2(accF0[0][i][0], F0[0], F0[1]);
        unp2(accF0[0][i][1], F0[2], F0[3]);
        unp2(accF1[0][i][0], F1[0], F1[1]);
        unp2(accF1[0][i][1], F1[2], F1[3]);
        float4 cc0 = *reinterpret_cast<const float4*>(&g_c_buf[base0]);
        float4 cc1 = *reinterpret_cast<const float4*>(&g_c_buf[base1]);
        const float* cc0p = (const float*)&cc0;
        const float* cc1p = (const float*)&cc1;
        float4 hv, cv;
        float* hp = (float*)&hv; float* cp = (float*)&cv;
#pragma unroll
        for (int q = 0; q < 4; q++) {
            int m = m0 + q;
            float iv = sigf(A[0][q] + bix[m] + bih[m]);
            float uv = tanhf(A[1][q] + bux[m] + buh[m]);
            float ov = sigf(A[2][q] + boxb[m] + boh[m]);
            float fx = A[3][q] + bfx[m] + bfh[m];
            float f0 = sigf(fx + F0[q]);
            float f1 = sigf(fx + F1[q]);
            float c = iv * uv + f0 * cc0p[q] + f1 * cc1p[q];
            cp[q] = c;
            hp[q] = ov * tanhf(c);
        }
        *reinterpret_cast<float4*>(&g_h_buf[base]) = hv;
        *reinterpret_cast<float4*>(&g_c_buf[base]) = cv;
        if (outp) {
            *reinterpret_cast<float4*>(&outp[(size_t)r * MDIM + m0]) = hv;
        }
    }
}

extern "C" void kernel_launch(void* const* d_in, const int* in_sizes, int n_in,
                              void* d_out, int out_size)
{
    const float* wte = nullptr;
    const float* rel = nullptr;
    const float* Wx[4];  int nWx = 0;   // ix, fx, ux, ox
    const float* Wh[4];  int nWh = 0;   // ih, fh, uh, oh
    const float* b256[8]; int nb = 0;   // bix,bfx,bux,box,bih,bfh,buh,boh
    const float* Wsih = nullptr;
    const float* Wshh = nullptr;
    const float* bseq[2]; int nbs = 0;  // b_seq_ih, b_seq_hh

    for (int i = 0; i < n_in; i++) {
        int s = in_sizes[i];
        const float* p = (const float*)d_in[i];
        switch (s) {
            case 33488896: wte = p; break;                 // 128*511*512
            case 4186112:  rel = p; break;                 // 128*511*64
            case 131072:   if (nWx < 4) Wx[nWx++] = p; break;   // 512*256
            case 65536:    if (nWh < 4) Wh[nWh++] = p; break;   // 256*256
            case 256:      if (nb < 8) b256[nb++] = p; break;
            case 327680:   Wsih = p; break;                // 320*1024
            case 262144:   Wshh = p; break;                // 256*1024
            case 1024:     if (nbs < 2) bseq[nbs++] = p; break;
            default: break;  // n_nodes (size 1) ignored: compile-time constant
        }
    }
    const float *Wix = Wx[0], *Wfx = Wx[1], *Wux = Wx[2], *Wox = Wx[3];
    const float *Wih = Wh[0], *Wfh = Wh[1], *Wuh = Wh[2], *Woh = Wh[3];
    const float *bix = b256[0], *bfx = b256[1], *bux = b256[2], *boxb = b256[3];
    const float *bih = b256[4], *bfh = b256[5], *buh = b256[6], *boh = b256[7];
    float* out = (float*)d_out;

    dim3 blk(NTH);

    // Level 8: all 256 leaves at once (32768 rows)
    k_leaf<<<dim3(512, 4), blk>>>(wte, Wix, Wux, Wox, bix, bux, boxb, bih, buh, boh);

    // Levels 7..0 (internal nodes)
    for (int L = 7; L >= 0; --L) {
        int P = 1 << L;
        int nodeBase = P - 1;
        int rowBlocks = (P * BATCH) / BM;
        dim3 grd(rowBlocks, 4);
        k_cell1<<<grd, blk>>>(rel, Wsih, bseq[0], bseq[1], nodeBase);
        k_cell2<<<grd, blk>>>(rel, Wsih, Wshh, bseq[0], bseq[1], nodeBase);
        k_gates<<<grd, blk>>>(wte, Wix, Wux, Wox, Wfx, Wih, Wuh, Woh, Wfh,
                              bix, bux, boxb, bfx, bih, buh, boh, bfh,
                              nodeBase, (L == 0) ? out : nullptr);
    }
}

// round 3
// speedup vs baseline: 1.2949x; 1.0726x over previous
#include <cuda_runtime.h>
#include <cuda_bf16.h>
#include <math.h>

// Problem constants (B=128, N=511, M=256, R=64, IN=512)
#define BATCH  128
#define NNODES 511
#define MDIM   256
#define RDIM   64
#define INDIM  512

// GEMM tiling
#define BM 64
#define BN 64
#define BK 16
#define SAS 66      // padded sA row stride (conflict-free, keeps 8B alignment)
#define NTH 256

typedef unsigned long long ull;

// Persistent scratch (device globals; no allocation)
__device__ float g_h_buf[(size_t)NNODES * BATCH * MDIM];   // [node][b][m]
__device__ float g_c_buf[(size_t)NNODES * BATCH * MDIM];
__device__ float g_h1[(size_t)128 * BATCH * MDIM];         // cell1 h   [levelrow][m]
__device__ float g_c1[(size_t)128 * BATCH * MDIM];         // cell1 c
__device__ float g_ht[(size_t)128 * BATCH * MDIM];         // h_tilde

__device__ __forceinline__ float sigf(float x) { return 1.0f / (1.0f + expf(-x)); }

// ---- packed f32x2 helpers (sm_103a FFMA2; ptxas never auto-emits this) ----
__device__ __forceinline__ ull pack2(float x) {
    ull r;
    unsigned u = __float_as_uint(x);
    asm("mov.b64 %0, {%1, %1};" : "=l"(r) : "r"(u));
    return r;
}
__device__ __forceinline__ void ffma2(ull& d, ull a, ull b) {
    asm("fma.rn.f32x2 %0, %1, %2, %0;" : "+l"(d) : "l"(a), "l"(b));
}
__device__ __forceinline__ void unp2(ull v, float& lo, float& hi) {
    unsigned l, h;
    asm("mov.b64 {%0, %1}, %2;" : "=r"(l), "=r"(h) : "l"(v));
    lo = __uint_as_float(l);
    hi = __uint_as_float(h);
}

// Multi-accumulator tiled GEMM phase with double-buffered smem (1 sync per
// BK-step) and register prefetch. acc[j][i][p] holds packed column pairs:
// lanes (2p, 2p+1). A rows come from per-row base pointers (gather support).
template<int NACC>
__device__ __forceinline__ void gemm_phase(
    ull (*acc)[4][2],
    const float* const* rowptr,
    const float* const (&Bp)[NACC],
    int ldb, int K,
    float* sA, float* sB, int tid)
{
    const int ty = tid >> 4, tx = tid & 15;
    const int ar = tid >> 2, akv = (tid & 3) * 4;
    const int bk = tid >> 4, bnv = (tid & 15) * 4;
    const float* aptr = rowptr[ar];
    const int ASZ = BK * SAS;
    const int BSZ = NACC * BK * BN;

    // prefetch tile 0
    float4 av = *reinterpret_cast<const float4*>(aptr + akv);
    float4 bv[NACC];
#pragma unroll
    for (int j = 0; j < NACC; j++)
        bv[j] = *reinterpret_cast<const float4*>(Bp[j] + (size_t)bk * ldb + bnv);

    // store tile 0 into buffer 0
    sA[(akv + 0) * SAS + ar] = av.x;
    sA[(akv + 1) * SAS + ar] = av.y;
    sA[(akv + 2) * SAS + ar] = av.z;
    sA[(akv + 3) * SAS + ar] = av.w;
#pragma unroll
    for (int j = 0; j < NACC; j++)
        *reinterpret_cast<float4*>(&sB[(j * BK + bk) * BN + bnv]) = bv[j];
    __syncthreads();

    int cur = 0;
    for (int k0 = 0; k0 < K; k0 += BK) {
        const bool more = (k0 + BK) < K;
        if (more) {
            av = *reinterpret_cast<const float4*>(aptr + k0 + BK + akv);
#pragma unroll
            for (int j = 0; j < NACC; j++)
                bv[j] = *reinterpret_cast<const float4*>(Bp[j] + (size_t)(k0 + BK + bk) * ldb + bnv);
        }
        const float* cA = sA + cur * ASZ;
        const float* cB = sB + cur * BSZ;
#pragma unroll
        for (int kk = 0; kk < BK; kk++) {
            // vectorized A fetch: 2x LDS.64 (8B-aligned since SAS is even)
            float2 alo = *reinterpret_cast<const float2*>(cA + kk * SAS + ty * 4);
            float2 ahi = *reinterpret_cast<const float2*>(cA + kk * SAS + ty * 4 + 2);
            ull a0 = pack2(alo.x);
            ull a1 = pack2(alo.y);
            ull a2 = pack2(ahi.x);
            ull a3 = pack2(ahi.y);
#pragma unroll
            for (int j = 0; j < NACC; j++) {
                ulonglong2 b = *reinterpret_cast<const ulonglong2*>(cB + (j * BK + kk) * BN + tx * 4);
                ffma2(acc[j][0][0], a0, b.x); ffma2(acc[j][0][1], a0, b.y);
                ffma2(acc[j][1][0], a1, b.x); ffma2(acc[j][1][1], a1, b.y);
                ffma2(acc[j][2][0], a2, b.x); ffma2(acc[j][2][1], a2, b.y);
                ffma2(acc[j][3][0], a3, b.x); ffma2(acc[j][3][1], a3, b.y);
            }
        }
        if (more) {
            const int nxt = cur ^ 1;
            float* nA = sA + nxt * ASZ;
            float* nB = sB + nxt * BSZ;
            nA[(akv + 0) * SAS + ar] = av.x;
            nA[(akv + 1) * SAS + ar] = av.y;
            nA[(akv + 2) * SAS + ar] = av.z;
            nA[(akv + 3) * SAS + ar] = av.w;
#pragma unroll
            for (int j = 0; j < NACC; j++)
                *reinterpret_cast<float4*>(&nB[(j * BK + bk) * BN + bnv]) = bv[j];
            __syncthreads();
            cur = nxt;
        }
    }
}

// ---------------- Leaf kernel: nodes 255..510 ----------------
__global__ void __launch_bounds__(NTH, 2)
k_leaf(const float* __restrict__ wte,
       const float* __restrict__ Wix, const float* __restrict__ Wux, const float* __restrict__ Wox,
       const float* __restrict__ bix, const float* __restrict__ bux, const float* __restrict__ boxb,
       const float* __restrict__ bih, const float* __restrict__ buh, const float* __restrict__ boh)
{
    __shared__ __align__(16) float sA[2 * BK * SAS];
    __shared__ __align__(16) float sB[2 * 3 * BK * BN];
    __shared__ const float* rowptr[BM];
    const int tid = threadIdx.x;
    const int rb = blockIdx.x * BM;
    const int n0 = blockIdx.y * BN;

    ull acc[3][4][2];
#pragma unroll
    for (int j = 0; j < 3; j++)
#pragma unroll
        for (int i = 0; i < 4; i++) { acc[j][i][0] = 0ull; acc[j][i][1] = 0ull; }

    if (tid < BM) {
        int r = rb + tid;
        int node = 255 + (r >> 7);
        int b = r & 127;
        rowptr[tid] = wte + (size_t)(b * NNODES + node) * INDIM;
    }
    __syncthreads();
    {
        const float* const Bp[3] = { Wix + n0, Wux + n0, Wox + n0 };
        gemm_phase<3>(acc, rowptr, Bp, MDIM, INDIM, sA, sB, tid);
    }
    const int ty = tid >> 4, tx = tid & 15;
    const int m0 = n0 + tx * 4;
#pragma unroll
    for (int i = 0; i < 4; i++) {
        int r = rb + ty * 4 + i;
        int node = 255 + (r >> 7);
        int b = r & 127;
        size_t base = (size_t)(node * BATCH + b) * MDIM + m0;
        float A[3][4];
#pragma unroll
        for (int j = 0; j < 3; j++) {
            unp2(acc[j][i][0], A[j][0], A[j][1]);
            unp2(acc[j][i][1], A[j][2], A[j][3]);
        }
        float4 hv, cv;
        float* hp = (float*)&hv; float* cp = (float*)&cv;
#pragma unroll
        for (int q = 0; q < 4; q++) {
            int m = m0 + q;
            float iv = sigf(A[0][q] + bix[m] + bih[m]);
            float uv = tanhf(A[1][q] + bux[m] + buh[m]);
            float ov = sigf(A[2][q] + boxb[m] + boh[m]);
            float c = iv * uv;
            cp[q] = c;
            hp[q] = ov * tanhf(c);
        }
        *reinterpret_cast<float4*>(&g_h_buf[base]) = hv;
        *reinterpret_cast<float4*>(&g_c_buf[base]) = cv;
    }
}

// ---------------- Cell 1: x = [h(2n+1), rel(2n+1)], h=c=0 (f-gate dead) ----------------
__global__ void __launch_bounds__(NTH, 2)
k_cell1(const float* __restrict__ rel,
        const float* __restrict__ Wsih,
        const float* __restrict__ bsi, const float* __restrict__ bsh,
        int nodeBase)
{
    __shared__ __align__(16) float sA[2 * BK * SAS];
    __shared__ __align__(16) float sB[2 * 3 * BK * BN];
    __shared__ const float* rowptr[BM];
    const int tid = threadIdx.x;
    const int rb = blockIdx.x * BM;
    const int n0 = blockIdx.y * BN;

    ull acc[3][4][2];  // i, g, o
#pragma unroll
    for (int j = 0; j < 3; j++)
#pragma unroll
        for (int i = 0; i < 4; i++) { acc[j][i][0] = 0ull; acc[j][i][1] = 0ull; }

    if (tid < BM) {
        int r = rb + tid;
        int node = nodeBase + (r >> 7);
        int b = r & 127;
        int c0 = 2 * node + 1;
        rowptr[tid] = g_h_buf + (size_t)(c0 * BATCH + b) * MDIM;
    }
    __syncthreads();
    {
        const float* const Bp[3] = { Wsih + n0, Wsih + 512 + n0, Wsih + 768 + n0 };
        gemm_phase<3>(acc, rowptr, Bp, 1024, MDIM, sA, sB, tid);
    }
    __syncthreads();
    if (tid < BM) {
        int r = rb + tid;
        int node = nodeBase + (r >> 7);
        int b = r & 127;
        int c0 = 2 * node + 1;
        rowptr[tid] = rel + (size_t)(b * NNODES + c0) * RDIM;
    }
    __syncthreads();
    {
        const float* const Bp[3] = { Wsih + 256 * 1024 + n0, Wsih + 256 * 1024 + 512 + n0,
                                     Wsih + 256 * 1024 + 768 + n0 };
        gemm_phase<3>(acc, rowptr, Bp, 1024, RDIM, sA, sB, tid);
    }
    const int ty = tid >> 4, tx = tid & 15;
    const int m0 = n0 + tx * 4;
#pragma unroll
    for (int i = 0; i < 4; i++) {
        int r = rb + ty * 4 + i;
        size_t base = (size_t)r * MDIM + m0;
        float A[3][4];
#pragma unroll
        for (int j = 0; j < 3; j++) {
            unp2(acc[j][i][0], A[j][0], A[j][1]);
            unp2(acc[j][i][1], A[j][2], A[j][3]);
        }
        float4 hv, cv;
        float* hp = (float*)&hv; float* cp = (float*)&cv;
#pragma unroll
        for (int q = 0; q < 4; q++) {
            int m = m0 + q;
            float iv = sigf(A[0][q] + bsi[m] + bsh[m]);
            float gv = tanhf(A[1][q] + bsi[512 + m] + bsh[512 + m]);
            float ov = sigf(A[2][q] + bsi[768 + m] + bsh[768 + m]);
            float c1 = iv * gv;
            cp[q] = c1;
            hp[q] = ov * tanhf(c1);
        }
        *reinterpret_cast<float4*>(&g_h1[base]) = hv;
        *reinterpret_cast<float4*>(&g_c1[base]) = cv;
    }
}

// ---------------- Cell 2: x = [h(2n+2), rel(2n+2)], h=h1, c=c1 ----------------
__global__ void __launch_bounds__(NTH, 2)
k_cell2(const float* __restrict__ rel,
        const float* __restrict__ Wsih, const float* __restrict__ Wshh,
        const float* __restrict__ bsi, const float* __restrict__ bsh,
        int nodeBase)
{
    __shared__ __align__(16) float sA[2 * BK * SAS];
    __shared__ __align__(16) float sB[2 * 4 * BK * BN];
    __shared__ const float* rowptr[BM];
    const int tid = threadIdx.x;
    const int rb = blockIdx.x * BM;
    const int n0 = blockIdx.y * BN;

    ull acc[4][4][2];  // i, f, g, o
#pragma unroll
    for (int j = 0; j < 4; j++)
#pragma unroll
        for (int i = 0; i < 4; i++) { acc[j][i][0] = 0ull; acc[j][i][1] = 0ull; }

    if (tid < BM) {
        int r = rb + tid;
        int node = nodeBase + (r >> 7);
        int b = r & 127;
        int c1n = 2 * node + 2;
        rowptr[tid] = g_h_buf + (size_t)(c1n * BATCH + b) * MDIM;
    }
    __syncthreads();
    {
        const float* const Bp[4] = { Wsih + n0, Wsih + 256 + n0, Wsih + 512 + n0, Wsih + 768 + n0 };
        gemm_phase<4>(acc, rowptr, Bp, 1024, MDIM, sA, sB, tid);
    }
    __syncthreads();
    if (tid < BM) {
        int r = rb + tid;
        int node = nodeBase + (r >> 7);
        int b = r & 127;
        int c1n = 2 * node + 2;
        rowptr[tid] = rel + (size_t)(b * NNODES + c1n) * RDIM;
    }
    __syncthreads();
    {
        const float* const Bp[4] = { Wsih + 256 * 1024 + n0, Wsih + 256 * 1024 + 256 + n0,
                                     Wsih + 256 * 1024 + 512 + n0, Wsih + 256 * 1024 + 768 + n0 };
        gemm_phase<4>(acc, rowptr, Bp, 1024, RDIM, sA, sB, tid);
    }
    __syncthreads();
    if (tid < BM) {
        int r = rb + tid;
        rowptr[tid] = g_h1 + (size_t)r * MDIM;
    }
    __syncthreads();
    {
        const float* const Bp[4] = { Wshh + n0, Wshh + 256 + n0, Wshh + 512 + n0, Wshh + 768 + n0 };
        gemm_phase<4>(acc, rowptr, Bp, 1024, MDIM, sA, sB, tid);
    }
    const int ty = tid >> 4, tx = tid & 15;
    const int m0 = n0 + tx * 4;
#pragma unroll
    for (int i = 0; i < 4; i++) {
        int r = rb + ty * 4 + i;
        size_t base = (size_t)r * MDIM + m0;
        float A[4][4];
#pragma unroll
        for (int j = 0; j < 4; j++) {
            unp2(acc[j][i][0], A[j][0], A[j][1]);
            unp2(acc[j][i][1], A[j][2], A[j][3]);
        }
        float4 c1v = *reinterpret_cast<const float4*>(&g_c1[base]);
        const float* c1p = (const float*)&c1v;
        float4 hv;
        float* hp = (float*)&hv;
#pragma unroll
        for (int q = 0; q < 4; q++) {
            int m = m0 + q;
            float iv = sigf(A[0][q] + bsi[m] + bsh[m]);
            float fv = sigf(A[1][q] + bsi[256 + m] + bsh[256 + m]);
            float gv = tanhf(A[2][q] + bsi[512 + m] + bsh[512 + m]);
            float ov = sigf(A[3][q] + bsi[768 + m] + bsh[768 + m]);
            float c2 = fv * c1p[q] + iv * gv;
            hp[q] = ov * tanhf(c2);
        }
        *reinterpret_cast<float4*>(&g_ht[base]) = hv;
    }
}

// ---------------- Tree gates: i,u,o,f0,f1 -> c, h ----------------
__global__ void __launch_bounds__(NTH, 2)
k_gates(const float* __restrict__ wte,
        const float* __restrict__ Wix, const float* __restrict__ Wux,
        const float* __restrict__ Wox, const float* __restrict__ Wfx,
        const float* __restrict__ Wih, const float* __restrict__ Wuh,
        const float* __restrict__ Woh, const float* __restrict__ Wfh,
        const float* __restrict__ bix, const float* __restrict__ bux,
        const float* __restrict__ boxb, const float* __restrict__ bfx,
        const float* __restrict__ bih, const float* __restrict__ buh,
        const float* __restrict__ boh, const float* __restrict__ bfh,
        int nodeBase, float* __restrict__ outp)
{
    __shared__ __align__(16) float sA[2 * BK * SAS];
    __shared__ __align__(16) float sB[2 * 4 * BK * BN];
    __shared__ const float* rowptr[BM];
    const int tid = threadIdx.x;
    const int rb = blockIdx.x * BM;
    const int n0 = blockIdx.y * BN;

    ull acc[4][4][2];   // i, u, o, fx
    ull accF0[1][4][2], accF1[1][4][2];
#pragma unroll
    for (int j = 0; j < 4; j++)
#pragma unroll
        for (int i = 0; i < 4; i++) { acc[j][i][0] = 0ull; acc[j][i][1] = 0ull; }
#pragma unroll
    for (int i = 0; i < 4; i++) {
        accF0[0][i][0] = 0ull; accF0[0][i][1] = 0ull;
        accF1[0][i][0] = 0ull; accF1[0][i][1] = 0ull;
    }

    // phase 1: x part (K = 512)
    if (tid < BM) {
        int r = rb + tid;
        int node = nodeBase + (r >> 7);
        int b = r & 127;
        rowptr[tid] = wte + (size_t)(b * NNODES + node) * INDIM;
    }
    __syncthreads();
    {
        const float* const Bp[4] = { Wix + n0, Wux + n0, Wox + n0, Wfx + n0 };
        gemm_phase<4>(acc, rowptr, Bp, MDIM, INDIM, sA, sB, tid);
    }
    // phase 2: h_tilde part for i,u,o (K = 256)
    __syncthreads();
    if (tid < BM) {
        int r = rb + tid;
        rowptr[tid] = g_ht + (size_t)r * MDIM;
    }
    __syncthreads();
    {
        const float* const Bp[3] = { Wih + n0, Wuh + n0, Woh + n0 };
        gemm_phase<3>(acc, rowptr, Bp, MDIM, MDIM, sA, sB, tid);
    }
    // phase 3: f0 = h(2n+1) @ Wfh
    __syncthreads();
    if (tid < BM) {
        int r = rb + tid;
        int node = nodeBase + (r >> 7);
        int b = r & 127;
        rowptr[tid] = g_h_buf + (size_t)((2 * node + 1) * BATCH + b) * MDIM;
    }
    __syncthreads();
    {
        const float* const Bp[1] = { Wfh + n0 };
        gemm_phase<1>(accF0, rowptr, Bp, MDIM, MDIM, sA, sB, tid);
    }
    // phase 4: f1 = h(2n+2) @ Wfh
    __syncthreads();
    if (tid < BM) {
        int r = rb + tid;
        int node = nodeBase + (r >> 7);
        int b = r & 127;
        rowptr[tid] = g_h_buf + (size_t)((2 * node + 2) * BATCH + b) * MDIM;
    }
    __syncthreads();
    {
        const float* const Bp[1] = { Wfh + n0 };
        gemm_phase<1>(accF1, rowptr, Bp, MDIM, MDIM, sA, sB, tid);
    }

    const int ty = tid >> 4, tx = tid & 15;
    const int m0 = n0 + tx * 4;
#pragma unroll
    for (int i = 0; i < 4; i++) {
        int r = rb + ty * 4 + i;
        int node = nodeBase + (r >> 7);
        int b = r & 127;
        int c0n = 2 * node + 1;
        int c1n = 2 * node + 2;
        size_t base  = (size_t)(node * BATCH + b) * MDIM + m0;
        size_t base0 = (size_t)(c0n * BATCH + b) * MDIM + m0;
        size_t base1 = (size_t)(c1n * BATCH + b) * MDIM + m0;
        float A[4][4], F0[4], F1[4];
#pragma unroll
        for (int j = 0; j < 4; j++) {
            unp2(acc[j][i][0], A[j][0], A[j][1]);
            unp2(acc[j][i][1], A[j][2], A[j][3]);
        }
        unp2(accF0[0][i][0], F0[0], F0[1]);
        unp2(accF0[0][i][1], F0[2], F0[3]);
        unp2(accF1[0][i][0], F1[0], F1[1]);
        unp2(accF1[0][i][1], F1[2], F1[3]);
        float4 cc0 = *reinterpret_cast<const float4*>(&g_c_buf[base0]);
        float4 cc1 = *reinterpret_cast<const float4*>(&g_c_buf[base1]);
        const float* cc0p = (const float*)&cc0;
        const float* cc1p = (const float*)&cc1;
        float4 hv, cv;
        float* hp = (float*)&hv; float* cp = (float*)&cv;
#pragma unroll
        for (int q = 0; q < 4; q++) {
            int m = m0 + q;
            float iv = sigf(A[0][q] + bix[m] + bih[m]);
            float uv = tanhf(A[1][q] + bux[m] + buh[m]);
            float ov = sigf(A[2][q] + boxb[m] + boh[m]);
            float fx = A[3][q] + bfx[m] + bfh[m];
            float f0 = sigf(fx + F0[q]);
            float f1 = sigf(fx + F1[q]);
            float c = iv * uv + f0 * cc0p[q] + f1 * cc1p[q];
            cp[q] = c;
            hp[q] = ov * tanhf(c);
        }
        *reinterpret_cast<float4*>(&g_h_buf[base]) = hv;
        *reinterpret_cast<float4*>(&g_c_buf[base]) = cv;
        if (outp) {
            *reinterpret_cast<float4*>(&outp[(size_t)r * MDIM + m0]) = hv;
        }
    }
}

extern "C" void kernel_launch(void* const* d_in, const int* in_sizes, int n_in,
                              void* d_out, int out_size)
{
    const float* wte = nullptr;
    const float* rel = nullptr;
    const float* Wx[4];  int nWx = 0;   // ix, fx, ux, ox
    const float* Wh[4];  int nWh = 0;   // ih, fh, uh, oh
    const float* b256[8]; int nb = 0;   // bix,bfx,bux,box,bih,bfh,buh,boh
    const float* Wsih = nullptr;
    const float* Wshh = nullptr;
    const float* bseq[2]; int nbs = 0;  // b_seq_ih, b_seq_hh

    for (int i = 0; i < n_in; i++) {
        int s = in_sizes[i];
        const float* p = (const float*)d_in[i];
        switch (s) {
            case 33488896: wte = p; break;                 // 128*511*512
            case 4186112:  rel = p; break;                 // 128*511*64
            case 131072:   if (nWx < 4) Wx[nWx++] = p; break;   // 512*256
            case 65536:    if (nWh < 4) Wh[nWh++] = p; break;   // 256*256
            case 256:      if (nb < 8) b256[nb++] = p; break;
            case 327680:   Wsih = p; break;                // 320*1024
            case 262144:   Wshh = p; break;                // 256*1024
            case 1024:     if (nbs < 2) bseq[nbs++] = p; break;
            default: break;  // n_nodes (size 1) ignored: compile-time constant
        }
    }
    const float *Wix = Wx[0], *Wfx = Wx[1], *Wux = Wx[2], *Wox = Wx[3];
    const float *Wih = Wh[0], *Wfh = Wh[1], *Wuh = Wh[2], *Woh = Wh[3];
    const float *bix = b256[0], *bfx = b256[1], *bux = b256[2], *boxb = b256[3];
    const float *bih = b256[4], *bfh = b256[5], *buh = b256[6], *boh = b256[7];
    float* out = (float*)d_out;

    dim3 blk(NTH);

    // Level 8: all 256 leaves at once (32768 rows)
    k_leaf<<<dim3(512, 4), blk>>>(wte, Wix, Wux, Wox, bix, bux, boxb, bih, buh, boh);

    // Levels 7..0 (internal nodes)
    for (int L = 7; L >= 0; --L) {
        int P = 1 << L;
        int nodeBase = P - 1;
        int rowBlocks = (P * BATCH) / BM;
        dim3 grd(rowBlocks, 4);
        k_cell1<<<grd, blk>>>(rel, Wsih, bseq[0], bseq[1], nodeBase);
        k_cell2<<<grd, blk>>>(rel, Wsih, Wshh, bseq[0], bseq[1], nodeBase);
        k_gates<<<grd, blk>>>(wte, Wix, Wux, Wox, Wfx, Wih, Wuh, Woh, Wfh,
                              bix, bux, boxb, bfx, bih, buh, boh, bfh,
                              nodeBase, (L == 0) ? out : nullptr);
    }
}